// round 12
// baseline (speedup 1.0000x reference)
#include <cuda_runtime.h>
#include <cstddef>
#include <cstdint>

#define BB 4
#define TT 4096
#define DD 1024
#define NN 64
#define RR 16
#define KK 4
#define BT (BB * TT)
#define SG 32    // g_dp tail padding (rows)
#define SG2 16   // scan prefetch group size (per chain)

// Scratch (device globals — no allocation allowed)
__device__ float g_mid[4 * 80 * BT];          // split-K partials, [kc][col][row]
__device__ float2 g_dp[BT * NN + SG * NN];    // interleaved {delta, proj}; padded tail
__device__ float g_states[BT * NN];
__device__ float g_wh[80 * DD];               // pre-split weights hi, [c][k]
__device__ float g_wl[80 * DD];               // pre-split weights lo

// ---------------------------------------------------------------------------
// tf32 helpers (fragment layout verified in rounds 8-11)
// ---------------------------------------------------------------------------
__device__ __forceinline__ uint32_t tf32_hi(float x) {
    uint32_t r;
    asm("cvt.rna.tf32.f32 %0, %1;" : "=r"(r) : "f"(x));
    return r;
}
__device__ __forceinline__ void mma_tf32(float4& d,
                                         uint32_t a0, uint32_t a1, uint32_t a2, uint32_t a3,
                                         uint32_t b0, uint32_t b1) {
    asm("mma.sync.aligned.m16n8k8.row.col.f32.tf32.tf32.f32 "
        "{%0,%1,%2,%3}, {%4,%5,%6,%7}, {%8,%9}, {%0,%1,%2,%3};"
        : "+f"(d.x), "+f"(d.y), "+f"(d.z), "+f"(d.w)
        : "r"(a0), "r"(a1), "r"(a2), "r"(a3), "r"(b0), "r"(b1));
}
// 3-pass split-tf32: D += alo*bhi + ahi*blo + ahi*bhi
#define MMA3(ACC, AH, AL, BH, BL)                                          \
    do {                                                                   \
        mma_tf32(ACC, AL[0], AL[1], AL[2], AL[3], BH[0], BH[1]);           \
        mma_tf32(ACC, AH[0], AH[1], AH[2], AH[3], BL[0], BL[1]);           \
        mma_tf32(ACC, AH[0], AH[1], AH[2], AH[3], BH[0], BH[1]);           \
    } while (0)

// ---------------------------------------------------------------------------
// Prep: split in_w/dt_w into tf32 hi/lo once. [c][k], c<64 -> in_w else dt_w.
// ---------------------------------------------------------------------------
__global__ void prep_w_kernel(const float* __restrict__ in_w,
                              const float* __restrict__ dt_w)
{
    int idx = blockIdx.x * 256 + threadIdx.x;
    if (idx >= 80 * DD) return;
    int c = idx >> 10, k = idx & (DD - 1);
    float v = (c < 64) ? in_w[(size_t)c * DD + k] : dt_w[(size_t)(c - 64) * DD + k];
    uint32_t h = tf32_hi(v);
    g_wh[idx] = __uint_as_float(h);
    g_wl[idx] = __uint_as_float(tf32_hi(v - __uint_as_float(h)));
}

// ---------------------------------------------------------------------------
// Stage 1a: split-K MMA partials. grid (4, 256): kc = K-chunk (256 wide),
// 64-row tile. Block 256 (8 warps). Warp tile 16 rows x 40 cols.
// dt cols (64..79, wn==1 nf>=3) use A = x instead of x+conv.
// ---------------------------------------------------------------------------
#define XP2 36    // [row][k] smem pitch
#define NROW 67   // 64 rows + 3 halo (idx 64..66 = t0-3..t0-1)

__global__ __launch_bounds__(256) void stage1a_kernel(
    const float* __restrict__ x,
    const float* __restrict__ conv_w)
{
    extern __shared__ float s1[];
    float* xsf = s1;                      // [67][36] fp32 x chunk
    float* ash = xsf + NROW * XP2;        // [64][36] tf32-hi of (x+conv)
    float* asl = ash + 64 * XP2;          // [64][36] tf32-lo
    float* xsh = asl + 64 * XP2;          // [64][36] tf32-hi of x
    float* xsl = xsh + 64 * XP2;          // [64][36] tf32-lo
    float* wbh = xsl + 64 * XP2;          // [80][36]  weights hi ([c][k])
    float* wbl = wbh + 80 * XP2;          // [80][36]  weights lo
    float* scw = wbl + 80 * XP2;          // [32][4] conv_w chunk

    const int tid = threadIdx.x;
    const int koff = blockIdx.x * 256;
    const int base = blockIdx.y * 64;        // global row (b*T + t)
    const int t0 = base & (TT - 1);
    const int warp = tid >> 5, lane = tid & 31;
    const int wm = warp & 3;                 // rows 16*wm
    const int wn = warp >> 2;                // cols 40*wn
    const int g = lane >> 2, tg = lane & 3;

    float4 acc[5];
#pragma unroll
    for (int j = 0; j < 5; j++) acc[j] = make_float4(0.f, 0.f, 0.f, 0.f);

    for (int k0 = koff; k0 < koff + 256; k0 += 32) {
        // ---- load x chunk [67 rows][32 k], row-major (coalesced float4) ----
        for (int idx = tid; idx < NROW * 8; idx += 256) {
            int ri = idx >> 3, kq = idx & 7;
            int t = (ri < 64) ? (t0 + ri) : (t0 + ri - NROW);  // 64..66 -> t0-3..t0-1
            float4 v = make_float4(0.f, 0.f, 0.f, 0.f);
            if (t >= 0)
                v = *(const float4*)(x + (size_t)(base - t0 + t) * DD + k0 + 4 * kq);
            *(float4*)(xsf + ri * XP2 + 4 * kq) = v;
        }
        // ---- copy pre-split weights (coalesced float4) ----
        for (int idx = tid; idx < 80 * 8; idx += 256) {
            int c = idx >> 3, kq = idx & 7;
            *(float4*)(wbh + c * XP2 + 4 * kq) =
                *(const float4*)(g_wh + (size_t)c * DD + k0 + 4 * kq);
            *(float4*)(wbl + c * XP2 + 4 * kq) =
                *(const float4*)(g_wl + (size_t)c * DD + k0 + 4 * kq);
        }
        // ---- conv_w chunk ----
        if (tid < 128) scw[tid] = conv_w[(size_t)(k0 + (tid >> 2)) * KK + (tid & 3)];
        __syncthreads();

        // ---- build conv + split both A operands ----
        for (int idx = tid; idx < 64 * 32; idx += 256) {
            int r = idx >> 5, kk = idx & 31;
            float xv = xsf[r * XP2 + kk];
            float c0 = scw[kk * 4 + 0], c1 = scw[kk * 4 + 1];
            float c2 = scw[kk * 4 + 2], c3 = scw[kk * 4 + 3];
            int rm1 = r - 1; if (rm1 < 0) rm1 += NROW;
            int rm2 = r - 2; if (rm2 < 0) rm2 += NROW;
            int rm3 = r - 3; if (rm3 < 0) rm3 += NROW;
            float v = fmaf(c3, xv, xv);
            v = fmaf(c2, xsf[rm1 * XP2 + kk], v);
            v = fmaf(c1, xsf[rm2 * XP2 + kk], v);
            v = fmaf(c0, xsf[rm3 * XP2 + kk], v);
            uint32_t ha = tf32_hi(v);
            ash[r * XP2 + kk] = __uint_as_float(ha);
            asl[r * XP2 + kk] = __uint_as_float(tf32_hi(v - __uint_as_float(ha)));
            uint32_t hx = tf32_hi(xv);
            xsh[r * XP2 + kk] = __uint_as_float(hx);
            xsl[r * XP2 + kk] = __uint_as_float(tf32_hi(xv - __uint_as_float(hx)));
        }
        __syncthreads();

        // ---- MMA: 4 k8 steps, warp tile 16x40 ----
#pragma unroll
        for (int ks = 0; ks < 4; ks++) {
            const int k8 = 8 * ks;
            const int r0 = 16 * wm + g;
            uint32_t cah[4], cal[4];
            cah[0] = __float_as_uint(ash[r0 * XP2 + k8 + tg]);
            cah[1] = __float_as_uint(ash[(r0 + 8) * XP2 + k8 + tg]);
            cah[2] = __float_as_uint(ash[r0 * XP2 + k8 + tg + 4]);
            cah[3] = __float_as_uint(ash[(r0 + 8) * XP2 + k8 + tg + 4]);
            cal[0] = __float_as_uint(asl[r0 * XP2 + k8 + tg]);
            cal[1] = __float_as_uint(asl[(r0 + 8) * XP2 + k8 + tg]);
            cal[2] = __float_as_uint(asl[r0 * XP2 + k8 + tg + 4]);
            cal[3] = __float_as_uint(asl[(r0 + 8) * XP2 + k8 + tg + 4]);
            uint32_t xah[4], xal[4];
            if (wn) {
                xah[0] = __float_as_uint(xsh[r0 * XP2 + k8 + tg]);
                xah[1] = __float_as_uint(xsh[(r0 + 8) * XP2 + k8 + tg]);
                xah[2] = __float_as_uint(xsh[r0 * XP2 + k8 + tg + 4]);
                xah[3] = __float_as_uint(xsh[(r0 + 8) * XP2 + k8 + tg + 4]);
                xal[0] = __float_as_uint(xsl[r0 * XP2 + k8 + tg]);
                xal[1] = __float_as_uint(xsl[(r0 + 8) * XP2 + k8 + tg]);
                xal[2] = __float_as_uint(xsl[r0 * XP2 + k8 + tg + 4]);
                xal[3] = __float_as_uint(xsl[(r0 + 8) * XP2 + k8 + tg + 4]);
            }
            uint32_t bh[5][2], bl[5][2];
#pragma unroll
            for (int nf = 0; nf < 5; nf++) {
                int c0 = 40 * wn + 8 * nf + g;
                bh[nf][0] = __float_as_uint(wbh[c0 * XP2 + k8 + tg]);
                bh[nf][1] = __float_as_uint(wbh[c0 * XP2 + k8 + tg + 4]);
                bl[nf][0] = __float_as_uint(wbl[c0 * XP2 + k8 + tg]);
                bl[nf][1] = __float_as_uint(wbl[c0 * XP2 + k8 + tg + 4]);
            }
            if (wn == 0) {
                MMA3(acc[0], cah, cal, bh[0], bl[0]);
                MMA3(acc[1], cah, cal, bh[1], bl[1]);
                MMA3(acc[2], cah, cal, bh[2], bl[2]);
                MMA3(acc[3], cah, cal, bh[3], bl[3]);
                MMA3(acc[4], cah, cal, bh[4], bl[4]);
            } else {
                MMA3(acc[0], cah, cal, bh[0], bl[0]);
                MMA3(acc[1], cah, cal, bh[1], bl[1]);
                MMA3(acc[2], cah, cal, bh[2], bl[2]);
                MMA3(acc[3], xah, xal, bh[3], bl[3]);
                MMA3(acc[4], xah, xal, bh[4], bl[4]);
            }
        }
        __syncthreads();
    }

    // ---- write partials to g_mid[kc][c][row] ----
    {
        float* mid = g_mid + (size_t)blockIdx.x * 80 * BT;
        size_t r0 = (size_t)base + 16 * wm + g;
#pragma unroll
        for (int nf = 0; nf < 5; nf++) {
            int c = 40 * wn + 8 * nf + 2 * tg;
            float4 v = acc[nf];
            mid[(size_t)c * BT + r0] = v.x;
            mid[(size_t)(c + 1) * BT + r0] = v.y;
            mid[(size_t)c * BT + r0 + 8] = v.z;
            mid[(size_t)(c + 1) * BT + r0 + 8] = v.w;
        }
    }
}

// ---------------------------------------------------------------------------
// Stage 1b: reduce partials, biases, tanh, tr_w GEMM; write interleaved g_dp.
// ---------------------------------------------------------------------------
__global__ __launch_bounds__(256) void stage1b_kernel(
    const float* __restrict__ in_b,
    const float* __restrict__ dt_b,
    const float* __restrict__ tr_w)
{
    __shared__ float sdm[64 * 16];
    __shared__ float str[16 * 64];
    __shared__ float sproj[64 * 68];   // [r][c], pitch 68

    const int tid = threadIdx.x;
    const int base = blockIdx.x * 64;
    const int cg = tid & 15;
    const int rg = tid >> 4;

    for (int idx = tid; idx < NN * RR; idx += 256) {
        int n = idx >> 4, r = idx & 15;
        str[r * 64 + n] = tr_w[idx];
    }

    float dtb = dt_b[cg];
#pragma unroll
    for (int i = 0; i < 4; i++) {
        size_t row = base + 4 * rg + i;
#pragma unroll
        for (int m = 0; m < 4; m++) {
            int c = cg + 16 * m;
            float v = in_b[c];
#pragma unroll
            for (int kc = 0; kc < 4; kc++)
                v += g_mid[((size_t)kc * 80 + c) * BT + row];
            sproj[(4 * rg + i) * 68 + c] = v;
        }
        float dm = dtb;
#pragma unroll
        for (int kc = 0; kc < 4; kc++)
            dm += g_mid[((size_t)kc * 80 + 64 + cg) * BT + row];
        sdm[(4 * rg + i) * 16 + cg] = tanhf(dm);
    }
    __syncthreads();

    float a2[4][4];
#pragma unroll
    for (int i = 0; i < 4; i++)
#pragma unroll
        for (int j = 0; j < 4; j++) a2[i][j] = 0.f;
#pragma unroll
    for (int r = 0; r < 16; r++) {
        float d0 = sdm[(4 * rg + 0) * 16 + r];
        float d1 = sdm[(4 * rg + 1) * 16 + r];
        float d2 = sdm[(4 * rg + 2) * 16 + r];
        float d3 = sdm[(4 * rg + 3) * 16 + r];
        float w0 = str[r * 64 + 4 * cg + 0];
        float w1 = str[r * 64 + 4 * cg + 1];
        float w2 = str[r * 64 + 4 * cg + 2];
        float w3 = str[r * 64 + 4 * cg + 3];
        a2[0][0] = fmaf(d0, w0, a2[0][0]); a2[0][1] = fmaf(d0, w1, a2[0][1]);
        a2[0][2] = fmaf(d0, w2, a2[0][2]); a2[0][3] = fmaf(d0, w3, a2[0][3]);
        a2[1][0] = fmaf(d1, w0, a2[1][0]); a2[1][1] = fmaf(d1, w1, a2[1][1]);
        a2[1][2] = fmaf(d1, w2, a2[1][2]); a2[1][3] = fmaf(d1, w3, a2[1][3]);
        a2[2][0] = fmaf(d2, w0, a2[2][0]); a2[2][1] = fmaf(d2, w1, a2[2][1]);
        a2[2][2] = fmaf(d2, w2, a2[2][2]); a2[2][3] = fmaf(d2, w3, a2[2][3]);
        a2[3][0] = fmaf(d3, w0, a2[3][0]); a2[3][1] = fmaf(d3, w1, a2[3][1]);
        a2[3][2] = fmaf(d3, w2, a2[3][2]); a2[3][3] = fmaf(d3, w3, a2[3][3]);
    }
#pragma unroll
    for (int i = 0; i < 4; i++) {
        size_t row = base + 4 * rg + i;
        const float* pr = sproj + (4 * rg + i) * 68 + 4 * cg;
        float4 v0 = make_float4(a2[i][0], pr[0], a2[i][1], pr[1]);
        float4 v1 = make_float4(a2[i][2], pr[2], a2[i][3], pr[3]);
        float* dst = (float*)(g_dp + row * NN + 4 * cg);
        *(float4*)(dst) = v0;
        *(float4*)(dst + 4) = v1;
    }
}

// ---------------------------------------------------------------------------
// Stage 2: sequential scan. 2 independent chains per lane (c, c+128) so the
// second chain's ops fill the first chain's MUFU/FFMA stall gaps (1 warp/SMSP
// has no other latency-hiding). 20-cycle chain per step:
//   h' = fmaf(h/2, tanh(h), h/2 + p/2 + d_next/2);  s = fmaf(h, th, h+p)
// grid 4 x 32 threads; SG2=16 double buffer per chain.
// ---------------------------------------------------------------------------
__device__ __forceinline__ float fast_tanh(float v) {
    float r;
    asm("tanh.approx.f32 %0, %1;" : "=f"(r) : "f"(v));
    return r;
}

__global__ __launch_bounds__(32) void scan_kernel()
{
    const int c0 = blockIdx.x * 32 + threadIdx.x;   // chains 0..127
    const int c1 = c0 + 128;                        // chains 128..255
    const float2* pdp0 = g_dp + (size_t)(c0 >> 6) * TT * NN + (c0 & 63);
    const float2* pdp1 = g_dp + (size_t)(c1 >> 6) * TT * NN + (c1 & 63);
    float* ps0 = g_states + (size_t)(c0 >> 6) * TT * NN + (c0 & 63);
    float* ps1 = g_states + (size_t)(c1 >> 6) * TT * NN + (c1 & 63);

    float2 A0[SG2], A1[SG2];
#pragma unroll
    for (int i = 0; i < SG2; i++) {
        A0[i] = pdp0[i * NN];
        A1[i] = pdp1[i * NN];
    }
    float h0 = 0.5f * A0[0].x;
    float h1 = 0.5f * A1[0].x;

    for (int t0 = 0; t0 < TT; t0 += SG2) {
        float2 B0[SG2], B1[SG2];
        int tn = t0 + SG2;
        // padded tail: reads past TT land in the pad region, values unused
#pragma unroll
        for (int i = 0; i < SG2; i++) {
            B0[i] = pdp0[(tn + i) * NN];
            B1[i] = pdp1[(tn + i) * NN];
        }
#pragma unroll
        for (int i = 0; i < SG2; i++) {
            // chain 0
            float p0 = A0[i].y;
            float dn0 = (i < SG2 - 1) ? A0[i + 1].x : B0[0].x;
            float th0 = fast_tanh(h0);                        // chain +16
            float h05 = 0.5f * h0;                            // off-chain
            float cc0 = fmaf(0.5f, dn0, fmaf(0.5f, p0, h05)); // off-chain
            ps0[(t0 + i) * NN] = fmaf(h0, th0, h0 + p0);      // off-chain
            h0 = fmaf(h05, th0, cc0);                         // chain +4
            // chain 1 (independent — fills chain 0's stall gaps)
            float p1 = A1[i].y;
            float dn1 = (i < SG2 - 1) ? A1[i + 1].x : B1[0].x;
            float th1 = fast_tanh(h1);
            float h15 = 0.5f * h1;
            float cc1 = fmaf(0.5f, dn1, fmaf(0.5f, p1, h15));
            ps1[(t0 + i) * NN] = fmaf(h1, th1, h1 + p1);
            h1 = fmaf(h15, th1, cc1);
        }
#pragma unroll
        for (int i = 0; i < SG2; i++) {
            A0[i] = B0[i];
            A1[i] = B1[i];
        }
    }
}

// ---------------------------------------------------------------------------
// Stage 3: out = states @ out_w^T + out_b via split-tf32 mma.sync.
// Block 128(M) x 64(N), 8 warps, warp tile 32x32 (2 m16 x 4 n8), K=64.
// (verified round 8, 50.6 us)
// ---------------------------------------------------------------------------
#define S3PAD 68

__global__ __launch_bounds__(256) void stage3_kernel(
    const float* __restrict__ out_w,
    const float* __restrict__ out_b,
    float* __restrict__ out)
{
    extern __shared__ float smem3[];
    float* sA = smem3;                 // [128][S3PAD]
    float* sB = smem3 + 128 * S3PAD;   // [64][S3PAD]

    const int tid = threadIdx.x;
    const int rbase = blockIdx.y * 128;
    const int cbase = blockIdx.x * 64;
    const int warp = tid >> 5;
    const int lane = tid & 31;
    const int wm = warp >> 1;
    const int wn = warp & 1;
    const int g = lane >> 2;
    const int tg = lane & 3;

    for (int idx = tid; idx < 128 * 16; idx += 256) {
        int r = idx >> 4, q = idx & 15;
        float4 v = *(const float4*)(g_states + (size_t)(rbase + r) * NN + 4 * q);
        *(float4*)(sA + r * S3PAD + 4 * q) = v;
    }
    for (int idx = tid; idx < 64 * 16; idx += 256) {
        int c = idx >> 4, q = idx & 15;
        float4 v = *(const float4*)(out_w + (size_t)(cbase + c) * NN + 4 * q);
        *(float4*)(sB + c * S3PAD + 4 * q) = v;
    }
    __syncthreads();

    float4 acc[2][4];
#pragma unroll
    for (int i = 0; i < 2; i++)
#pragma unroll
        for (int j = 0; j < 4; j++) acc[i][j] = make_float4(0.f, 0.f, 0.f, 0.f);

#pragma unroll
    for (int k0 = 0; k0 < 64; k0 += 8) {
        uint32_t ahi[2][4], alo[2][4];
#pragma unroll
        for (int mf = 0; mf < 2; mf++) {
            int r0 = wm * 32 + mf * 16 + g;
            float av[4];
            av[0] = sA[r0 * S3PAD + k0 + tg];
            av[1] = sA[(r0 + 8) * S3PAD + k0 + tg];
            av[2] = sA[r0 * S3PAD + k0 + tg + 4];
            av[3] = sA[(r0 + 8) * S3PAD + k0 + tg + 4];
#pragma unroll
            for (int q = 0; q < 4; q++) {
                uint32_t h = tf32_hi(av[q]);
                ahi[mf][q] = h;
                alo[mf][q] = tf32_hi(av[q] - __uint_as_float(h));
            }
        }
        uint32_t bhi[4][2], blo[4][2];
#pragma unroll
        for (int nf = 0; nf < 4; nf++) {
            int c0 = wn * 32 + nf * 8 + g;
            float bv[2];
            bv[0] = sB[c0 * S3PAD + k0 + tg];
            bv[1] = sB[c0 * S3PAD + k0 + tg + 4];
#pragma unroll
            for (int q = 0; q < 2; q++) {
                uint32_t h = tf32_hi(bv[q]);
                bhi[nf][q] = h;
                blo[nf][q] = tf32_hi(bv[q] - __uint_as_float(h));
            }
        }
#pragma unroll
        for (int mf = 0; mf < 2; mf++) {
#pragma unroll
            for (int nf = 0; nf < 4; nf++) {
                MMA3(acc[mf][nf], ahi[mf], alo[mf], bhi[nf], blo[nf]);
            }
        }
    }

#pragma unroll
    for (int nf = 0; nf < 4; nf++) {
        int c = cbase + wn * 32 + nf * 8 + 2 * tg;
        float b0 = out_b[c], b1 = out_b[c + 1];
#pragma unroll
        for (int mf = 0; mf < 2; mf++) {
            int r0 = rbase + wm * 32 + mf * 16 + g;
            float4 v = acc[mf][nf];
            *(float2*)(out + (size_t)r0 * DD + c) = make_float2(v.x + b0, v.y + b1);
            *(float2*)(out + (size_t)(r0 + 8) * DD + c) = make_float2(v.z + b0, v.w + b1);
        }
    }
}

// ---------------------------------------------------------------------------
extern "C" void kernel_launch(void* const* d_in, const int* in_sizes, int n_in,
                              void* d_out, int out_size)
{
    const float* x      = (const float*)d_in[0];
    const float* conv_w = (const float*)d_in[1];
    const float* in_w   = (const float*)d_in[2];
    const float* in_b   = (const float*)d_in[3];
    const float* dt_w   = (const float*)d_in[4];
    const float* dt_b   = (const float*)d_in[5];
    const float* tr_w   = (const float*)d_in[6];
    const float* out_w  = (const float*)d_in[7];
    const float* out_b  = (const float*)d_in[8];
    float* out = (float*)d_out;

    const int s1_smem = (NROW * XP2 + 4 * 64 * XP2 + 2 * 80 * XP2 + 128)
                        * sizeof(float);   // 70064 B
    cudaFuncSetAttribute(stage1a_kernel,
                         cudaFuncAttributeMaxDynamicSharedMemorySize, s1_smem);
    const int s3_smem = (128 + 64) * S3PAD * sizeof(float);  // 52224 B
    cudaFuncSetAttribute(stage3_kernel,
                         cudaFuncAttributeMaxDynamicSharedMemorySize, s3_smem);

    prep_w_kernel<<<320, 256>>>(in_w, dt_w);
    stage1a_kernel<<<dim3(4, 256), 256, s1_smem>>>(x, conv_w);
    stage1b_kernel<<<256, 256>>>(in_b, dt_b, tr_w);
    scan_kernel<<<4, 32>>>();
    stage3_kernel<<<dim3(16, 128), 256, s3_smem>>>(out_w, out_b, out);
}

// round 13
// speedup vs baseline: 1.1959x; 1.1959x over previous
#include <cuda_runtime.h>
#include <cstddef>
#include <cstdint>

#define BB 4
#define TT 4096
#define DD 1024
#define NN 64
#define RR 16
#define KK 4
#define BT (BB * TT)
#define SG 32    // scan prefetch group size

// Scratch (device globals — no allocation allowed)
__device__ float g_mid[4 * 80 * BT];          // split-K partials, [kc][col][row]
__device__ float2 g_dp[BT * NN + SG * NN];    // interleaved {delta, proj}; padded tail
__device__ float g_states[BT * NN];
__device__ float g_wh[80 * DD];               // pre-split in_w/dt_w hi, [c][k]
__device__ float g_wl[80 * DD];               // pre-split in_w/dt_w lo
__device__ float g_owh[DD * NN];              // pre-split out_w hi, [c][k]
__device__ float g_owl[DD * NN];              // pre-split out_w lo

// ---------------------------------------------------------------------------
// tf32 helpers (fragment layout verified in rounds 8-12)
// ---------------------------------------------------------------------------
__device__ __forceinline__ uint32_t tf32_hi(float x) {
    uint32_t r;
    asm("cvt.rna.tf32.f32 %0, %1;" : "=r"(r) : "f"(x));
    return r;
}
__device__ __forceinline__ void mma_tf32(float4& d,
                                         uint32_t a0, uint32_t a1, uint32_t a2, uint32_t a3,
                                         uint32_t b0, uint32_t b1) {
    asm("mma.sync.aligned.m16n8k8.row.col.f32.tf32.tf32.f32 "
        "{%0,%1,%2,%3}, {%4,%5,%6,%7}, {%8,%9}, {%0,%1,%2,%3};"
        : "+f"(d.x), "+f"(d.y), "+f"(d.z), "+f"(d.w)
        : "r"(a0), "r"(a1), "r"(a2), "r"(a3), "r"(b0), "r"(b1));
}
// 3-pass split-tf32: D += alo*bhi + ahi*blo + ahi*bhi
#define MMA3(ACC, AH, AL, BH, BL)                                          \
    do {                                                                   \
        mma_tf32(ACC, AL[0], AL[1], AL[2], AL[3], BH[0], BH[1]);           \
        mma_tf32(ACC, AH[0], AH[1], AH[2], AH[3], BL[0], BL[1]);           \
        mma_tf32(ACC, AH[0], AH[1], AH[2], AH[3], BH[0], BH[1]);           \
    } while (0)

// ---------------------------------------------------------------------------
// Prep: split in_w/dt_w AND out_w into tf32 hi/lo once.
// idx < 80*DD: gemm1 weights [c][k]. idx >= 80*DD: out_w [c][k] (c<1024,k<64).
// ---------------------------------------------------------------------------
__global__ void prep_w_kernel(const float* __restrict__ in_w,
                              const float* __restrict__ dt_w,
                              const float* __restrict__ out_w)
{
    int idx = blockIdx.x * 256 + threadIdx.x;
    if (idx < 80 * DD) {
        int c = idx >> 10, k = idx & (DD - 1);
        float v = (c < 64) ? in_w[(size_t)c * DD + k]
                           : dt_w[(size_t)(c - 64) * DD + k];
        uint32_t h = tf32_hi(v);
        g_wh[idx] = __uint_as_float(h);
        g_wl[idx] = __uint_as_float(tf32_hi(v - __uint_as_float(h)));
    } else if (idx < 80 * DD + DD * NN) {
        int j = idx - 80 * DD;
        float v = out_w[j];
        uint32_t h = tf32_hi(v);
        g_owh[j] = __uint_as_float(h);
        g_owl[j] = __uint_as_float(tf32_hi(v - __uint_as_float(h)));
    }
}

// ---------------------------------------------------------------------------
// Stage 1a: split-K MMA partials. grid (4, 256). Block 256 (8 warps).
// Warp tile 16 rows x 40 cols. dt cols (wn==1 nf>=3) use A = x.
// ---------------------------------------------------------------------------
#define XP2 36    // [row][k] smem pitch
#define NROW 67   // 64 rows + 3 halo (idx 64..66 = t0-3..t0-1)

__global__ __launch_bounds__(256) void stage1a_kernel(
    const float* __restrict__ x,
    const float* __restrict__ conv_w)
{
    extern __shared__ float s1[];
    float* xsf = s1;                      // [67][36] fp32 x chunk
    float* ash = xsf + NROW * XP2;        // [64][36] tf32-hi of (x+conv)
    float* asl = ash + 64 * XP2;          // [64][36] tf32-lo
    float* xsh = asl + 64 * XP2;          // [64][36] tf32-hi of x
    float* xsl = xsh + 64 * XP2;          // [64][36] tf32-lo
    float* wbh = xsl + 64 * XP2;          // [80][36]  weights hi ([c][k])
    float* wbl = wbh + 80 * XP2;          // [80][36]  weights lo
    float* scw = wbl + 80 * XP2;          // [32][4] conv_w chunk

    const int tid = threadIdx.x;
    const int koff = blockIdx.x * 256;
    const int base = blockIdx.y * 64;        // global row (b*T + t)
    const int t0 = base & (TT - 1);
    const int warp = tid >> 5, lane = tid & 31;
    const int wm = warp & 3;                 // rows 16*wm
    const int wn = warp >> 2;                // cols 40*wn
    const int g = lane >> 2, tg = lane & 3;

    float4 acc[5];
#pragma unroll
    for (int j = 0; j < 5; j++) acc[j] = make_float4(0.f, 0.f, 0.f, 0.f);

    for (int k0 = koff; k0 < koff + 256; k0 += 32) {
        // ---- load x chunk [67 rows][32 k], row-major (coalesced float4) ----
        for (int idx = tid; idx < NROW * 8; idx += 256) {
            int ri = idx >> 3, kq = idx & 7;
            int t = (ri < 64) ? (t0 + ri) : (t0 + ri - NROW);  // 64..66 -> t0-3..t0-1
            float4 v = make_float4(0.f, 0.f, 0.f, 0.f);
            if (t >= 0)
                v = *(const float4*)(x + (size_t)(base - t0 + t) * DD + k0 + 4 * kq);
            *(float4*)(xsf + ri * XP2 + 4 * kq) = v;
        }
        // ---- copy pre-split weights (coalesced float4) ----
        for (int idx = tid; idx < 80 * 8; idx += 256) {
            int c = idx >> 3, kq = idx & 7;
            *(float4*)(wbh + c * XP2 + 4 * kq) =
                *(const float4*)(g_wh + (size_t)c * DD + k0 + 4 * kq);
            *(float4*)(wbl + c * XP2 + 4 * kq) =
                *(const float4*)(g_wl + (size_t)c * DD + k0 + 4 * kq);
        }
        // ---- conv_w chunk ----
        if (tid < 128) scw[tid] = conv_w[(size_t)(k0 + (tid >> 2)) * KK + (tid & 3)];
        __syncthreads();

        // ---- build conv + split both A operands ----
        for (int idx = tid; idx < 64 * 32; idx += 256) {
            int r = idx >> 5, kk = idx & 31;
            float xv = xsf[r * XP2 + kk];
            float c0 = scw[kk * 4 + 0], c1 = scw[kk * 4 + 1];
            float c2 = scw[kk * 4 + 2], c3 = scw[kk * 4 + 3];
            int rm1 = r - 1; if (rm1 < 0) rm1 += NROW;
            int rm2 = r - 2; if (rm2 < 0) rm2 += NROW;
            int rm3 = r - 3; if (rm3 < 0) rm3 += NROW;
            float v = fmaf(c3, xv, xv);
            v = fmaf(c2, xsf[rm1 * XP2 + kk], v);
            v = fmaf(c1, xsf[rm2 * XP2 + kk], v);
            v = fmaf(c0, xsf[rm3 * XP2 + kk], v);
            uint32_t ha = tf32_hi(v);
            ash[r * XP2 + kk] = __uint_as_float(ha);
            asl[r * XP2 + kk] = __uint_as_float(tf32_hi(v - __uint_as_float(ha)));
            uint32_t hx = tf32_hi(xv);
            xsh[r * XP2 + kk] = __uint_as_float(hx);
            xsl[r * XP2 + kk] = __uint_as_float(tf32_hi(xv - __uint_as_float(hx)));
        }
        __syncthreads();

        // ---- MMA: 4 k8 steps, warp tile 16x40 ----
#pragma unroll
        for (int ks = 0; ks < 4; ks++) {
            const int k8 = 8 * ks;
            const int r0 = 16 * wm + g;
            uint32_t cah[4], cal[4];
            cah[0] = __float_as_uint(ash[r0 * XP2 + k8 + tg]);
            cah[1] = __float_as_uint(ash[(r0 + 8) * XP2 + k8 + tg]);
            cah[2] = __float_as_uint(ash[r0 * XP2 + k8 + tg + 4]);
            cah[3] = __float_as_uint(ash[(r0 + 8) * XP2 + k8 + tg + 4]);
            cal[0] = __float_as_uint(asl[r0 * XP2 + k8 + tg]);
            cal[1] = __float_as_uint(asl[(r0 + 8) * XP2 + k8 + tg]);
            cal[2] = __float_as_uint(asl[r0 * XP2 + k8 + tg + 4]);
            cal[3] = __float_as_uint(asl[(r0 + 8) * XP2 + k8 + tg + 4]);
            uint32_t xah[4], xal[4];
            if (wn) {
                xah[0] = __float_as_uint(xsh[r0 * XP2 + k8 + tg]);
                xah[1] = __float_as_uint(xsh[(r0 + 8) * XP2 + k8 + tg]);
                xah[2] = __float_as_uint(xsh[r0 * XP2 + k8 + tg + 4]);
                xah[3] = __float_as_uint(xsh[(r0 + 8) * XP2 + k8 + tg + 4]);
                xal[0] = __float_as_uint(xsl[r0 * XP2 + k8 + tg]);
                xal[1] = __float_as_uint(xsl[(r0 + 8) * XP2 + k8 + tg]);
                xal[2] = __float_as_uint(xsl[r0 * XP2 + k8 + tg + 4]);
                xal[3] = __float_as_uint(xsl[(r0 + 8) * XP2 + k8 + tg + 4]);
            }
            uint32_t bh[5][2], bl[5][2];
#pragma unroll
            for (int nf = 0; nf < 5; nf++) {
                int c0 = 40 * wn + 8 * nf + g;
                bh[nf][0] = __float_as_uint(wbh[c0 * XP2 + k8 + tg]);
                bh[nf][1] = __float_as_uint(wbh[c0 * XP2 + k8 + tg + 4]);
                bl[nf][0] = __float_as_uint(wbl[c0 * XP2 + k8 + tg]);
                bl[nf][1] = __float_as_uint(wbl[c0 * XP2 + k8 + tg + 4]);
            }
            if (wn == 0) {
                MMA3(acc[0], cah, cal, bh[0], bl[0]);
                MMA3(acc[1], cah, cal, bh[1], bl[1]);
                MMA3(acc[2], cah, cal, bh[2], bl[2]);
                MMA3(acc[3], cah, cal, bh[3], bl[3]);
                MMA3(acc[4], cah, cal, bh[4], bl[4]);
            } else {
                MMA3(acc[0], cah, cal, bh[0], bl[0]);
                MMA3(acc[1], cah, cal, bh[1], bl[1]);
                MMA3(acc[2], cah, cal, bh[2], bl[2]);
                MMA3(acc[3], xah, xal, bh[3], bl[3]);
                MMA3(acc[4], xah, xal, bh[4], bl[4]);
            }
        }
        __syncthreads();
    }

    // ---- write partials to g_mid[kc][c][row] ----
    {
        float* mid = g_mid + (size_t)blockIdx.x * 80 * BT;
        size_t r0 = (size_t)base + 16 * wm + g;
#pragma unroll
        for (int nf = 0; nf < 5; nf++) {
            int c = 40 * wn + 8 * nf + 2 * tg;
            float4 v = acc[nf];
            mid[(size_t)c * BT + r0] = v.x;
            mid[(size_t)(c + 1) * BT + r0] = v.y;
            mid[(size_t)c * BT + r0 + 8] = v.z;
            mid[(size_t)(c + 1) * BT + r0 + 8] = v.w;
        }
    }
}

// ---------------------------------------------------------------------------
// Stage 1b: reduce partials, biases, tanh, tr_w GEMM; write interleaved g_dp.
// ---------------------------------------------------------------------------
__global__ __launch_bounds__(256) void stage1b_kernel(
    const float* __restrict__ in_b,
    const float* __restrict__ dt_b,
    const float* __restrict__ tr_w)
{
    __shared__ float sdm[64 * 16];
    __shared__ float str[16 * 64];
    __shared__ float sproj[64 * 68];   // [r][c], pitch 68

    const int tid = threadIdx.x;
    const int base = blockIdx.x * 64;
    const int cg = tid & 15;
    const int rg = tid >> 4;

    for (int idx = tid; idx < NN * RR; idx += 256) {
        int n = idx >> 4, r = idx & 15;
        str[r * 64 + n] = tr_w[idx];
    }

    float dtb = dt_b[cg];
#pragma unroll
    for (int i = 0; i < 4; i++) {
        size_t row = base + 4 * rg + i;
#pragma unroll
        for (int m = 0; m < 4; m++) {
            int c = cg + 16 * m;
            float v = in_b[c];
#pragma unroll
            for (int kc = 0; kc < 4; kc++)
                v += g_mid[((size_t)kc * 80 + c) * BT + row];
            sproj[(4 * rg + i) * 68 + c] = v;
        }
        float dm = dtb;
#pragma unroll
        for (int kc = 0; kc < 4; kc++)
            dm += g_mid[((size_t)kc * 80 + 64 + cg) * BT + row];
        sdm[(4 * rg + i) * 16 + cg] = tanhf(dm);
    }
    __syncthreads();

    float a2[4][4];
#pragma unroll
    for (int i = 0; i < 4; i++)
#pragma unroll
        for (int j = 0; j < 4; j++) a2[i][j] = 0.f;
#pragma unroll
    for (int r = 0; r < 16; r++) {
        float d0 = sdm[(4 * rg + 0) * 16 + r];
        float d1 = sdm[(4 * rg + 1) * 16 + r];
        float d2 = sdm[(4 * rg + 2) * 16 + r];
        float d3 = sdm[(4 * rg + 3) * 16 + r];
        float w0 = str[r * 64 + 4 * cg + 0];
        float w1 = str[r * 64 + 4 * cg + 1];
        float w2 = str[r * 64 + 4 * cg + 2];
        float w3 = str[r * 64 + 4 * cg + 3];
        a2[0][0] = fmaf(d0, w0, a2[0][0]); a2[0][1] = fmaf(d0, w1, a2[0][1]);
        a2[0][2] = fmaf(d0, w2, a2[0][2]); a2[0][3] = fmaf(d0, w3, a2[0][3]);
        a2[1][0] = fmaf(d1, w0, a2[1][0]); a2[1][1] = fmaf(d1, w1, a2[1][1]);
        a2[1][2] = fmaf(d1, w2, a2[1][2]); a2[1][3] = fmaf(d1, w3, a2[1][3]);
        a2[2][0] = fmaf(d2, w0, a2[2][0]); a2[2][1] = fmaf(d2, w1, a2[2][1]);
        a2[2][2] = fmaf(d2, w2, a2[2][2]); a2[2][3] = fmaf(d2, w3, a2[2][3]);
        a2[3][0] = fmaf(d3, w0, a2[3][0]); a2[3][1] = fmaf(d3, w1, a2[3][1]);
        a2[3][2] = fmaf(d3, w2, a2[3][2]); a2[3][3] = fmaf(d3, w3, a2[3][3]);
    }
#pragma unroll
    for (int i = 0; i < 4; i++) {
        size_t row = base + 4 * rg + i;
        const float* pr = sproj + (4 * rg + i) * 68 + 4 * cg;
        float4 v0 = make_float4(a2[i][0], pr[0], a2[i][1], pr[1]);
        float4 v1 = make_float4(a2[i][2], pr[2], a2[i][3], pr[3]);
        float* dst = (float*)(g_dp + row * NN + 4 * cg);
        *(float4*)(dst) = v0;
        *(float4*)(dst + 4) = v1;
    }
}

// ---------------------------------------------------------------------------
// Stage 2: sequential scan — EXACT round-8 form (measured best in context).
// silu(y) = h*(1 + tanh(h)), h = y/2  =>  s' = fmaf(h, tanh(h), h + p)
// 8 blocks x 32 threads, SG=32 double buffer of float2 {d/2, p}.
// ---------------------------------------------------------------------------
__device__ __forceinline__ float fast_tanh(float v) {
    float r;
    asm("tanh.approx.f32 %0, %1;" : "=f"(r) : "f"(v));
    return r;
}

__global__ __launch_bounds__(32) void scan_kernel()
{
    const int chain = blockIdx.x * 32 + threadIdx.x;   // 8 blocks x 32 threads
    const int b = chain >> 6;
    const int n = chain & 63;
    const float2* pdp = g_dp + (size_t)b * TT * NN + n;
    float* ps = g_states + (size_t)b * TT * NN + n;

    float s = 0.f;

    float2 dpA[SG];   // .x = d/2, .y = p
#pragma unroll
    for (int i = 0; i < SG; i++) {
        float2 v = pdp[i * NN];
        dpA[i] = make_float2(0.5f * v.x, v.y);
    }

    for (int t0 = 0; t0 < TT; t0 += SG) {
        float2 dpB[SG];
        int tn = t0 + SG;
        // padded tail: reads past TT land in the pad region, values unused
#pragma unroll
        for (int i = 0; i < SG; i++) dpB[i] = pdp[(tn + i) * NN];
#pragma unroll
        for (int i = 0; i < SG; i++) {
            float hd = dpA[i].x, p = dpA[i].y;
            float h = fmaf(s, 0.5f, hd);     // chain +4
            float th = fast_tanh(h);         // +16
            float hp = h + p;                // off-chain
            s = fmaf(h, th, hp);             // +4
            ps[(t0 + i) * NN] = s;
        }
#pragma unroll
        for (int i = 0; i < SG; i++) {
            dpA[i] = make_float2(0.5f * dpB[i].x, dpB[i].y);
        }
    }
}

// ---------------------------------------------------------------------------
// Stage 3: out = states @ out_w^T + out_b via split-tf32 mma.sync.
// v2: hi/lo split done ONCE cooperatively into smem (A) / pre-split in prep (B).
// Inner loop = pure LDS + MMA (no cvt). Block 128x64, 8 warps, K=64.
// ---------------------------------------------------------------------------
#define S3PAD 68

__global__ __launch_bounds__(256) void stage3_kernel(
    const float* __restrict__ out_b,
    float* __restrict__ out)
{
    extern __shared__ float smem3[];
    float* sAh = smem3;                   // [128][S3PAD]
    float* sAl = sAh + 128 * S3PAD;       // [128][S3PAD]
    float* sBh = sAl + 128 * S3PAD;       // [64][S3PAD]
    float* sBl = sBh + 64 * S3PAD;        // [64][S3PAD]

    const int tid = threadIdx.x;
    const int rbase = blockIdx.y * 128;
    const int cbase = blockIdx.x * 64;
    const int warp = tid >> 5;
    const int lane = tid & 31;
    const int wm = warp >> 1;
    const int wn = warp & 1;
    const int g = lane >> 2;
    const int tg = lane & 3;

    // load + split A (once per element)
    for (int idx = tid; idx < 128 * 16; idx += 256) {
        int r = idx >> 4, q = idx & 15;
        float4 v = *(const float4*)(g_states + (size_t)(rbase + r) * NN + 4 * q);
        float vv[4] = {v.x, v.y, v.z, v.w};
        float hh[4], ll[4];
#pragma unroll
        for (int j = 0; j < 4; j++) {
            uint32_t h = tf32_hi(vv[j]);
            hh[j] = __uint_as_float(h);
            ll[j] = __uint_as_float(tf32_hi(vv[j] - __uint_as_float(h)));
        }
        *(float4*)(sAh + r * S3PAD + 4 * q) = make_float4(hh[0], hh[1], hh[2], hh[3]);
        *(float4*)(sAl + r * S3PAD + 4 * q) = make_float4(ll[0], ll[1], ll[2], ll[3]);
    }
    // load pre-split B (straight copies)
    for (int idx = tid; idx < 64 * 16; idx += 256) {
        int c = idx >> 4, q = idx & 15;
        *(float4*)(sBh + c * S3PAD + 4 * q) =
            *(const float4*)(g_owh + (size_t)(cbase + c) * NN + 4 * q);
        *(float4*)(sBl + c * S3PAD + 4 * q) =
            *(const float4*)(g_owl + (size_t)(cbase + c) * NN + 4 * q);
    }
    __syncthreads();

    float4 acc[2][4];
#pragma unroll
    for (int i = 0; i < 2; i++)
#pragma unroll
        for (int j = 0; j < 4; j++) acc[i][j] = make_float4(0.f, 0.f, 0.f, 0.f);

#pragma unroll
    for (int k0 = 0; k0 < 64; k0 += 8) {
        uint32_t ahi[2][4], alo[2][4];
#pragma unroll
        for (int mf = 0; mf < 2; mf++) {
            int r0 = wm * 32 + mf * 16 + g;
            ahi[mf][0] = __float_as_uint(sAh[r0 * S3PAD + k0 + tg]);
            ahi[mf][1] = __float_as_uint(sAh[(r0 + 8) * S3PAD + k0 + tg]);
            ahi[mf][2] = __float_as_uint(sAh[r0 * S3PAD + k0 + tg + 4]);
            ahi[mf][3] = __float_as_uint(sAh[(r0 + 8) * S3PAD + k0 + tg + 4]);
            alo[mf][0] = __float_as_uint(sAl[r0 * S3PAD + k0 + tg]);
            alo[mf][1] = __float_as_uint(sAl[(r0 + 8) * S3PAD + k0 + tg]);
            alo[mf][2] = __float_as_uint(sAl[r0 * S3PAD + k0 + tg + 4]);
            alo[mf][3] = __float_as_uint(sAl[(r0 + 8) * S3PAD + k0 + tg + 4]);
        }
        uint32_t bhi[4][2], blo[4][2];
#pragma unroll
        for (int nf = 0; nf < 4; nf++) {
            int c0 = wn * 32 + nf * 8 + g;
            bhi[nf][0] = __float_as_uint(sBh[c0 * S3PAD + k0 + tg]);
            bhi[nf][1] = __float_as_uint(sBh[c0 * S3PAD + k0 + tg + 4]);
            blo[nf][0] = __float_as_uint(sBl[c0 * S3PAD + k0 + tg]);
            blo[nf][1] = __float_as_uint(sBl[c0 * S3PAD + k0 + tg + 4]);
        }
#pragma unroll
        for (int mf = 0; mf < 2; mf++) {
#pragma unroll
            for (int nf = 0; nf < 4; nf++) {
                MMA3(acc[mf][nf], ahi[mf], alo[mf], bhi[nf], blo[nf]);
            }
        }
    }

#pragma unroll
    for (int nf = 0; nf < 4; nf++) {
        int c = cbase + wn * 32 + nf * 8 + 2 * tg;
        float b0 = out_b[c], b1 = out_b[c + 1];
#pragma unroll
        for (int mf = 0; mf < 2; mf++) {
            int r0 = rbase + wm * 32 + mf * 16 + g;
            float4 v = acc[mf][nf];
            *(float2*)(out + (size_t)r0 * DD + c) = make_float2(v.x + b0, v.y + b1);
            *(float2*)(out + (size_t)(r0 + 8) * DD + c) = make_float2(v.z + b0, v.w + b1);
        }
    }
}

// ---------------------------------------------------------------------------
extern "C" void kernel_launch(void* const* d_in, const int* in_sizes, int n_in,
                              void* d_out, int out_size)
{
    const float* x      = (const float*)d_in[0];
    const float* conv_w = (const float*)d_in[1];
    const float* in_w   = (const float*)d_in[2];
    const float* in_b   = (const float*)d_in[3];
    const float* dt_w   = (const float*)d_in[4];
    const float* dt_b   = (const float*)d_in[5];
    const float* tr_w   = (const float*)d_in[6];
    const float* out_w  = (const float*)d_in[7];
    const float* out_b  = (const float*)d_in[8];
    float* out = (float*)d_out;

    const int s1_smem = (NROW * XP2 + 4 * 64 * XP2 + 2 * 80 * XP2 + 128)
                        * sizeof(float);   // 70064 B
    cudaFuncSetAttribute(stage1a_kernel,
                         cudaFuncAttributeMaxDynamicSharedMemorySize, s1_smem);
    const int s3_smem = (2 * 128 + 2 * 64) * S3PAD * sizeof(float);  // 104448 B
    cudaFuncSetAttribute(stage3_kernel,
                         cudaFuncAttributeMaxDynamicSharedMemorySize, s3_smem);

    // prep: 80*1024 (gemm1 w) + 1024*64 (out_w) = 147456 elements
    prep_w_kernel<<<576, 256>>>(in_w, dt_w, out_w);
    stage1a_kernel<<<dim3(4, 256), 256, s1_smem>>>(x, conv_w);
    stage1b_kernel<<<256, 256>>>(in_b, dt_b, tr_w);
    scan_kernel<<<8, 32>>>();
    stage3_kernel<<<dim3(16, 128), 256, s3_smem>>>(out_b, out);
}